// round 1
// baseline (speedup 1.0000x reference)
#include <cuda_runtime.h>
#include <math.h>

// Problem constants
#define Bn   8
#define Hh   32
#define Ww   32
#define Cc   192
#define DI   384
#define Ss   16
#define Rr   12
#define HID  768
#define Ll   1024          // H*W
#define ROWS (Bn * Ll)     // 8192

// ---------------- scratch (no allocation allowed) ----------------
__device__ float g_hx   [ROWS * Cc];
__device__ float g_xz   [ROWS * (2 * DI)];
__device__ float g_u    [ROWS * DI];
__device__ float g_xdbl [ROWS * 44];
__device__ float g_delta[ROWS * DI];
__device__ float g_y    [ROWS * DI];
__device__ float g_xmid [ROWS * Cc];
__device__ float g_h2   [ROWS * Cc];
__device__ float g_m    [ROWS * HID];

// ---------------- device math helpers ----------------
__device__ __forceinline__ float silu_f(float x) {
    return x / (1.0f + __expf(-x));
}
__device__ __forceinline__ float softplus_f(float x) {
    return (x > 20.0f) ? x : log1pf(expf(x));
}
__device__ __forceinline__ float gelu_f(float x) {
    // tanh approximation (jax.nn.gelu default approximate=True)
    float x3 = x * x * x;
    return 0.5f * x * (1.0f + tanhf(0.7978845608028654f * (x + 0.044715f * x3)));
}

// ---------------- LayerNorm (one block per row, blockDim == C) ----------------
template <int C>
__global__ void ln_kernel(const float* __restrict__ x,
                          const float* __restrict__ g,
                          const float* __restrict__ b,
                          float* __restrict__ out) {
    int row = blockIdx.x;
    int t   = threadIdx.x;
    float v = x[row * C + t];
    float s = v, s2 = v * v;
    __shared__ float sh[C / 32], sh2[C / 32];
#pragma unroll
    for (int o = 16; o; o >>= 1) {
        s  += __shfl_xor_sync(0xffffffffu, s,  o);
        s2 += __shfl_xor_sync(0xffffffffu, s2, o);
    }
    if ((t & 31) == 0) { sh[t >> 5] = s; sh2[t >> 5] = s2; }
    __syncthreads();
    float mean = 0.f, m2 = 0.f;
#pragma unroll
    for (int i = 0; i < C / 32; i++) { mean += sh[i]; m2 += sh2[i]; }
    mean *= (1.0f / C);
    float var = m2 * (1.0f / C) - mean * mean;
    float inv = rsqrtf(var + 1e-5f);
    out[row * C + t] = (v - mean) * inv * g[t] + b[t];
}

// ---------------- out_norm LN + silu(z) gating (C = DI = 384) ----------------
__global__ void gate_ln_kernel(const float* __restrict__ y,
                               const float* __restrict__ xz,
                               const float* __restrict__ g,
                               const float* __restrict__ b,
                               float* __restrict__ out) {
    int row = blockIdx.x;
    int t   = threadIdx.x;           // 384
    float v = y[row * DI + t];
    float s = v, s2 = v * v;
    __shared__ float sh[DI / 32], sh2[DI / 32];
#pragma unroll
    for (int o = 16; o; o >>= 1) {
        s  += __shfl_xor_sync(0xffffffffu, s,  o);
        s2 += __shfl_xor_sync(0xffffffffu, s2, o);
    }
    if ((t & 31) == 0) { sh[t >> 5] = s; sh2[t >> 5] = s2; }
    __syncthreads();
    float mean = 0.f, m2 = 0.f;
#pragma unroll
    for (int i = 0; i < DI / 32; i++) { mean += sh[i]; m2 += sh2[i]; }
    mean *= (1.0f / DI);
    float var = m2 * (1.0f / DI) - mean * mean;
    float inv = rsqrtf(var + 1e-5f);
    float ln  = (v - mean) * inv * g[t] + b[t];
    float zz  = xz[row * (2 * DI) + DI + t];
    out[row * DI + t] = ln * silu_f(zz);
}

// ---------------- tiled GEMM: C[M,N] = A[M,K(lda)] * W[N,K]^T (+bias)(+act)(+res)
// ACT: 0 none, 1 softplus, 2 gelu
#define BM 64
#define BN 64
#define BK 16

template <int ACT, bool HAS_BIAS, bool HAS_RES>
__global__ __launch_bounds__(256)
void gemm_kernel(const float* __restrict__ A, int lda,
                 const float* __restrict__ W,
                 const float* __restrict__ bias,
                 const float* __restrict__ res,
                 float* __restrict__ Cout,
                 int M, int N, int K) {
    __shared__ float As[BK][BM + 4];
    __shared__ float Ws[BK][BN + 4];
    int t  = threadIdx.x;
    int tx = t & 15;       // N dir
    int ty = t >> 4;       // M dir
    int row0 = blockIdx.y * BM;
    int col0 = blockIdx.x * BN;
    float acc[4][4] = {};

    for (int k0 = 0; k0 < K; k0 += BK) {
#pragma unroll
        for (int i = 0; i < 4; i++) {
            int e  = t + i * 256;
            int r  = e >> 4;
            int kk = e & 15;
            int k  = k0 + kk;
            As[kk][r] = (k < K) ? A[(row0 + r) * lda + k] : 0.f;
        }
#pragma unroll
        for (int i = 0; i < 4; i++) {
            int e  = t + i * 256;
            int n  = e >> 4;
            int kk = e & 15;
            int k  = k0 + kk;
            int col = col0 + n;
            Ws[kk][n] = (k < K && col < N) ? W[col * K + k] : 0.f;
        }
        __syncthreads();
#pragma unroll
        for (int kk = 0; kk < BK; kk++) {
            float a[4], w[4];
#pragma unroll
            for (int i = 0; i < 4; i++) a[i] = As[kk][ty * 4 + i];
#pragma unroll
            for (int j = 0; j < 4; j++) w[j] = Ws[kk][tx * 4 + j];
#pragma unroll
            for (int i = 0; i < 4; i++)
#pragma unroll
                for (int j = 0; j < 4; j++)
                    acc[i][j] = fmaf(a[i], w[j], acc[i][j]);
        }
        __syncthreads();
    }

#pragma unroll
    for (int i = 0; i < 4; i++) {
        int r = row0 + ty * 4 + i;
#pragma unroll
        for (int j = 0; j < 4; j++) {
            int c = col0 + tx * 4 + j;
            if (c < N) {
                float v = acc[i][j];
                if (HAS_BIAS) v += bias[c];
                if (ACT == 1) v = softplus_f(v);
                else if (ACT == 2) v = gelu_f(v);
                if (HAS_RES) v += res[r * N + c];
                Cout[r * N + c] = v;
            }
        }
    }
}

// ---------------- depthwise 3x3 conv + bias + SiLU, scatter to zigzag order ----
__global__ void conv_silu_kernel(const float* __restrict__ xz,
                                 const float* __restrict__ cw,
                                 const float* __restrict__ cb,
                                 const int* __restrict__ perm_rev,
                                 float* __restrict__ u) {
    int bp = blockIdx.x;            // b*1024 + p
    int b  = bp >> 10;
    int p  = bp & 1023;
    int h  = p >> 5;
    int w  = p & 31;
    int d  = threadIdx.x;           // 384
    float acc = cb[d];
#pragma unroll
    for (int kh = 0; kh < 3; kh++) {
        int nh = h + kh - 1;
        if ((unsigned)nh >= (unsigned)Hh) continue;
#pragma unroll
        for (int kw = 0; kw < 3; kw++) {
            int nw = w + kw - 1;
            if ((unsigned)nw >= (unsigned)Ww) continue;
            acc = fmaf(cw[d * 9 + kh * 3 + kw],
                       xz[((b << 10) + (nh << 5) + nw) * (2 * DI) + d], acc);
        }
    }
    u[((b << 10) + perm_rev[p]) * DI + d] = silu_f(acc);
}

// ---------------- selective scan: one 16-lane group per (b,d) -----------------
__global__ void scan_kernel(const float* __restrict__ xdbl,
                            const float* __restrict__ delta,
                            const float* __restrict__ u,
                            const float* __restrict__ A_log,
                            const float* __restrict__ Dp,
                            const int* __restrict__ perm,
                            float* __restrict__ y) {
    int t = threadIdx.x;                  // 256
    int g = blockIdx.x * 16 + (t >> 4);   // group id: 0..3071
    int s = t & 15;
    int b = g / DI;
    int d = g % DI;
    float A  = -expf(A_log[d * Ss + s]);
    float Dd = Dp[d];
    float h  = 0.f;
    int base = b * Ll;
    for (int l = 0; l < Ll; l++) {
        int row  = base + l;
        float dl = delta[row * DI + d];
        float ul = u[row * DI + d];
        float Bs = xdbl[row * 44 + Rr + s];
        float Cs = xdbl[row * 44 + Rr + Ss + s];
        float dA = __expf(dl * A);
        h = fmaf(dA, h, dl * ul * Bs);
        float yv = h * Cs;
#pragma unroll
        for (int o = 8; o; o >>= 1) yv += __shfl_xor_sync(0xffffffffu, yv, o, 16);
        if (s == 0) y[(base + perm[l]) * DI + d] = yv + ul * Dd;
    }
}

// ---------------- launcher ----------------
extern "C" void kernel_launch(void* const* d_in, const int* in_sizes, int n_in,
                              void* d_out, int out_size) {
    const float* x          = (const float*)d_in[0];
    const int*   perm       = (const int*)  d_in[1];
    const int*   perm_rev   = (const int*)  d_in[2];
    const float* ln1_g      = (const float*)d_in[3];
    const float* ln1_b      = (const float*)d_in[4];
    const float* in_proj_w  = (const float*)d_in[5];
    const float* conv_w     = (const float*)d_in[6];
    const float* conv_b     = (const float*)d_in[7];
    const float* x_proj_w   = (const float*)d_in[8];
    const float* dt_proj_w  = (const float*)d_in[9];
    const float* dt_proj_b  = (const float*)d_in[10];
    const float* A_log      = (const float*)d_in[11];
    const float* Dp         = (const float*)d_in[12];
    const float* out_norm_g = (const float*)d_in[13];
    const float* out_norm_b = (const float*)d_in[14];
    const float* out_proj_w = (const float*)d_in[15];
    const float* ln2_g      = (const float*)d_in[16];
    const float* ln2_b      = (const float*)d_in[17];
    const float* fc1_w      = (const float*)d_in[18];
    const float* fc1_b      = (const float*)d_in[19];
    const float* fc2_w      = (const float*)d_in[20];
    const float* fc2_b      = (const float*)d_in[21];
    float* out = (float*)d_out;

    float *hx, *xz, *u, *xdbl, *delta, *y, *xmid, *h2, *m;
    cudaGetSymbolAddress((void**)&hx,    g_hx);
    cudaGetSymbolAddress((void**)&xz,    g_xz);
    cudaGetSymbolAddress((void**)&u,     g_u);
    cudaGetSymbolAddress((void**)&xdbl,  g_xdbl);
    cudaGetSymbolAddress((void**)&delta, g_delta);
    cudaGetSymbolAddress((void**)&y,     g_y);
    cudaGetSymbolAddress((void**)&xmid,  g_xmid);
    cudaGetSymbolAddress((void**)&h2,    g_h2);
    cudaGetSymbolAddress((void**)&m,     g_m);

    // 1. LN1
    ln_kernel<Cc><<<ROWS, Cc>>>(x, ln1_g, ln1_b, hx);
    // 2. in_proj: [8192,192] x [768,192]^T -> xz [8192,768]
    gemm_kernel<0, false, false><<<dim3((2 * DI) / BN, ROWS / BM), 256>>>(
        hx, Cc, in_proj_w, nullptr, nullptr, xz, ROWS, 2 * DI, Cc);
    // 3. depthwise conv + SiLU + zigzag scatter -> u [8192,384]
    conv_silu_kernel<<<ROWS, DI>>>(xz, conv_w, conv_b, perm_rev, u);
    // 4. x_proj: [8192,384] x [44,384]^T -> xdbl [8192,44]
    gemm_kernel<0, false, false><<<dim3(1, ROWS / BM), 256>>>(
        u, DI, x_proj_w, nullptr, nullptr, xdbl, ROWS, 44, DI);
    // 5. dt_proj (+bias, softplus): [8192,12(stride44)] x [384,12]^T -> delta
    gemm_kernel<1, true, false><<<dim3(DI / BN, ROWS / BM), 256>>>(
        xdbl, 44, dt_proj_w, dt_proj_b, nullptr, delta, ROWS, DI, Rr);
    // 6. selective scan + Dp skip + un-zigzag scatter -> y (spatial order)
    scan_kernel<<<(Bn * DI) / 16, 256>>>(xdbl, delta, u, A_log, Dp, perm, y);
    // 7. out_norm LN + silu(z) gate (in-place on y)
    gate_ln_kernel<<<ROWS, DI>>>(y, xz, out_norm_g, out_norm_b, y);
    // 8. out_proj + residual x -> xmid [8192,192]
    gemm_kernel<0, false, true><<<dim3(Cc / BN, ROWS / BM), 256>>>(
        y, DI, out_proj_w, nullptr, x, xmid, ROWS, Cc, DI);
    // 9. LN2
    ln_kernel<Cc><<<ROWS, Cc>>>(xmid, ln2_g, ln2_b, h2);
    // 10. fc1 + bias + gelu -> m [8192,768]
    gemm_kernel<2, true, false><<<dim3(HID / BN, ROWS / BM), 256>>>(
        h2, Cc, fc1_w, fc1_b, nullptr, m, ROWS, HID, Cc);
    // 11. fc2 + bias + residual xmid -> out [8192,192]
    gemm_kernel<0, true, true><<<dim3(Cc / BN, ROWS / BM), 256>>>(
        m, HID, fc2_w, fc2_b, xmid, out, ROWS, Cc, HID);
}

// round 2
// speedup vs baseline: 1.0209x; 1.0209x over previous
#include <cuda_runtime.h>
#include <math.h>

// Problem constants
#define Bn   8
#define Hh   32
#define Ww   32
#define Cc   192
#define DI   384
#define Ss   16
#define Rr   12
#define HID  768
#define Ll   1024          // H*W
#define ROWS (Bn * Ll)     // 8192

// ---------------- scratch (no allocation allowed) ----------------
__device__ float g_hx   [ROWS * Cc];
__device__ float g_xz   [ROWS * (2 * DI)];
__device__ float g_u    [ROWS * DI];
__device__ float g_xdbl [ROWS * 44];
__device__ float g_delta[ROWS * DI];
__device__ float g_y    [ROWS * DI];
__device__ float g_xmid [ROWS * Cc];
__device__ float g_h2   [ROWS * Cc];
__device__ float g_m    [ROWS * HID];

// ---------------- device math helpers ----------------
__device__ __forceinline__ float silu_f(float x) {
    return x / (1.0f + __expf(-x));
}
__device__ __forceinline__ float softplus_f(float x) {
    return (x > 20.0f) ? x : log1pf(expf(x));
}
__device__ __forceinline__ float gelu_f(float x) {
    float x3 = x * x * x;
    return 0.5f * x * (1.0f + tanhf(0.7978845608028654f * (x + 0.044715f * x3)));
}

// ---------------- LayerNorm (one block per row, blockDim == C) ----------------
template <int C>
__global__ void ln_kernel(const float* __restrict__ x,
                          const float* __restrict__ g,
                          const float* __restrict__ b,
                          float* __restrict__ out) {
    int row = blockIdx.x;
    int t   = threadIdx.x;
    float v = x[row * C + t];
    float s = v, s2 = v * v;
    __shared__ float sh[C / 32], sh2[C / 32];
#pragma unroll
    for (int o = 16; o; o >>= 1) {
        s  += __shfl_xor_sync(0xffffffffu, s,  o);
        s2 += __shfl_xor_sync(0xffffffffu, s2, o);
    }
    if ((t & 31) == 0) { sh[t >> 5] = s; sh2[t >> 5] = s2; }
    __syncthreads();
    float mean = 0.f, m2 = 0.f;
#pragma unroll
    for (int i = 0; i < C / 32; i++) { mean += sh[i]; m2 += sh2[i]; }
    mean *= (1.0f / C);
    float var = m2 * (1.0f / C) - mean * mean;
    float inv = rsqrtf(var + 1e-5f);
    out[row * C + t] = (v - mean) * inv * g[t] + b[t];
}

// ---------------- out_norm LN + silu(z) gating (C = DI = 384) ----------------
__global__ void gate_ln_kernel(const float* __restrict__ y,
                               const float* __restrict__ xz,
                               const float* __restrict__ g,
                               const float* __restrict__ b,
                               float* __restrict__ out) {
    int row = blockIdx.x;
    int t   = threadIdx.x;           // 384
    float v = y[row * DI + t];
    float s = v, s2 = v * v;
    __shared__ float sh[DI / 32], sh2[DI / 32];
#pragma unroll
    for (int o = 16; o; o >>= 1) {
        s  += __shfl_xor_sync(0xffffffffu, s,  o);
        s2 += __shfl_xor_sync(0xffffffffu, s2, o);
    }
    if ((t & 31) == 0) { sh[t >> 5] = s; sh2[t >> 5] = s2; }
    __syncthreads();
    float mean = 0.f, m2 = 0.f;
#pragma unroll
    for (int i = 0; i < DI / 32; i++) { mean += sh[i]; m2 += sh2[i]; }
    mean *= (1.0f / DI);
    float var = m2 * (1.0f / DI) - mean * mean;
    float inv = rsqrtf(var + 1e-5f);
    float ln  = (v - mean) * inv * g[t] + b[t];
    float zz  = xz[row * (2 * DI) + DI + t];
    out[row * DI + t] = ln * silu_f(zz);
}

// ================= GEMM v2: C[M,N] = A[M,K(lda)] * W[N,K]^T =================
// 128x64 tile, 256 threads, 8x4 micro-tile, float4 loads, reg-prefetch pipeline.
// Requires: M%128==0, N%64==0, K%16==0, lda%4==0. (all call sites verified)
// ACT: 0 none, 1 softplus, 2 gelu
#define GBM 128
#define GBN 64
#define GBK 16

template <int ACT, bool HAS_BIAS, bool HAS_RES>
__global__ __launch_bounds__(256)
void gemm2_kernel(const float* __restrict__ A, int lda,
                  const float* __restrict__ W,
                  const float* __restrict__ bias,
                  const float* __restrict__ res,
                  float* __restrict__ Cout,
                  int M, int N, int K) {
    __shared__ float As[GBK][GBM + 4];   // [k][m]
    __shared__ float Ws[GBK][GBN + 4];   // [k][n]
    int t    = threadIdx.x;
    int tx   = t & 15;          // N dir: 16 * 4 = 64
    int ty   = t >> 4;          // M dir: 16 * 8 = 128
    int row0 = blockIdx.y * GBM;
    int col0 = blockIdx.x * GBN;

    // load-thread mapping
    int a_r0 = t >> 2;          // 0..63 (iter 0), +64 (iter 1)
    int kc4  = (t & 3) * 4;     // k offset within tile (0,4,8,12)
    int w_n  = t >> 2;          // 0..63

    float acc[8][4] = {};
    float4 ra[2], rw;

    // prologue: fetch k0 = 0
    ra[0] = *(const float4*)&A[(row0 + a_r0) * lda + kc4];
    ra[1] = *(const float4*)&A[(row0 + a_r0 + 64) * lda + kc4];
    rw    = *(const float4*)&W[(col0 + w_n) * K + kc4];

    for (int k0 = 0; k0 < K; k0 += GBK) {
        __syncthreads();
        // stage regs -> smem (transposed)
        As[kc4 + 0][a_r0]      = ra[0].x;
        As[kc4 + 1][a_r0]      = ra[0].y;
        As[kc4 + 2][a_r0]      = ra[0].z;
        As[kc4 + 3][a_r0]      = ra[0].w;
        As[kc4 + 0][a_r0 + 64] = ra[1].x;
        As[kc4 + 1][a_r0 + 64] = ra[1].y;
        As[kc4 + 2][a_r0 + 64] = ra[1].z;
        As[kc4 + 3][a_r0 + 64] = ra[1].w;
        Ws[kc4 + 0][w_n] = rw.x;
        Ws[kc4 + 1][w_n] = rw.y;
        Ws[kc4 + 2][w_n] = rw.z;
        Ws[kc4 + 3][w_n] = rw.w;
        __syncthreads();

        // prefetch next k-tile into regs
        int kn = k0 + GBK;
        if (kn < K) {
            ra[0] = *(const float4*)&A[(row0 + a_r0) * lda + kn + kc4];
            ra[1] = *(const float4*)&A[(row0 + a_r0 + 64) * lda + kn + kc4];
            rw    = *(const float4*)&W[(col0 + w_n) * K + kn + kc4];
        }

#pragma unroll
        for (int kk = 0; kk < GBK; kk++) {
            float a[8], w[4];
            *(float4*)&a[0] = *(const float4*)&As[kk][ty * 8];
            *(float4*)&a[4] = *(const float4*)&As[kk][ty * 8 + 4];
            *(float4*)&w[0] = *(const float4*)&Ws[kk][tx * 4];
#pragma unroll
            for (int i = 0; i < 8; i++)
#pragma unroll
                for (int j = 0; j < 4; j++)
                    acc[i][j] = fmaf(a[i], w[j], acc[i][j]);
        }
    }

    // epilogue
    int col = col0 + tx * 4;
    float4 bv = make_float4(0.f, 0.f, 0.f, 0.f);
    if (HAS_BIAS) bv = *(const float4*)&bias[col];
#pragma unroll
    for (int i = 0; i < 8; i++) {
        int r = row0 + ty * 8 + i;
        float4 v;
        v.x = acc[i][0] + bv.x;
        v.y = acc[i][1] + bv.y;
        v.z = acc[i][2] + bv.z;
        v.w = acc[i][3] + bv.w;
        if (ACT == 1) { v.x = softplus_f(v.x); v.y = softplus_f(v.y);
                        v.z = softplus_f(v.z); v.w = softplus_f(v.w); }
        else if (ACT == 2) { v.x = gelu_f(v.x); v.y = gelu_f(v.y);
                             v.z = gelu_f(v.z); v.w = gelu_f(v.w); }
        if (HAS_RES) {
            float4 rv = *(const float4*)&res[r * N + col];
            v.x += rv.x; v.y += rv.y; v.z += rv.z; v.w += rv.w;
        }
        *(float4*)&Cout[r * N + col] = v;
    }
}

// ---------------- depthwise 3x3 conv + bias + SiLU, scatter to zigzag order ----
__global__ void conv_silu_kernel(const float* __restrict__ xz,
                                 const float* __restrict__ cw,
                                 const float* __restrict__ cb,
                                 const int* __restrict__ perm_rev,
                                 float* __restrict__ u) {
    int bp = blockIdx.x;            // b*1024 + p
    int b  = bp >> 10;
    int p  = bp & 1023;
    int h  = p >> 5;
    int w  = p & 31;
    int d  = threadIdx.x;           // 384
    float acc = cb[d];
#pragma unroll
    for (int kh = 0; kh < 3; kh++) {
        int nh = h + kh - 1;
        if ((unsigned)nh >= (unsigned)Hh) continue;
#pragma unroll
        for (int kw = 0; kw < 3; kw++) {
            int nw = w + kw - 1;
            if ((unsigned)nw >= (unsigned)Ww) continue;
            acc = fmaf(cw[d * 9 + kh * 3 + kw],
                       xz[((b << 10) + (nh << 5) + nw) * (2 * DI) + d], acc);
        }
    }
    u[((b << 10) + perm_rev[p]) * DI + d] = silu_f(acc);
}

// ========== fused x_proj + dt_proj + softplus (16 rows per block) ==========
__global__ __launch_bounds__(256)
void xdt_kernel(const float* __restrict__ u,
                const float* __restrict__ xw,     // [44,384]
                const float* __restrict__ dtw,    // [384,12]
                const float* __restrict__ dtb,    // [384]
                float* __restrict__ xdbl,         // [ROWS,44]
                float* __restrict__ delta) {      // [ROWS,DI]
    __shared__ float su[16][DI + 4];
    __shared__ float sdt[16][12];
    int t    = threadIdx.x;
    int row0 = blockIdx.x * 16;

    // load u rows: 16*384 floats = 1536 float4, 6 per thread
#pragma unroll
    for (int i = 0; i < 6; i++) {
        int idx = t + i * 256;      // float4 index
        int r   = idx / 96;
        int c4  = (idx % 96) * 4;
        *(float4*)&su[r][c4] = *(const float4*)&u[(row0 + r) * DI + c4];
    }
    __syncthreads();

    // x_proj: 16 rows x 44 cols = 704 dots of K=384
#pragma unroll
    for (int p = 0; p < 3; p++) {
        int idx = t + p * 256;
        if (idx < 704) {
            int r = idx & 15;
            int c = idx >> 4;       // 0..43
            const float* wr = &xw[c * DI];
            float acc = 0.f;
#pragma unroll 4
            for (int k = 0; k < DI; k += 4) {
                float4 uv = *(const float4*)&su[r][k];
                float4 wv = *(const float4*)&wr[k];
                acc = fmaf(uv.x, wv.x, acc);
                acc = fmaf(uv.y, wv.y, acc);
                acc = fmaf(uv.z, wv.z, acc);
                acc = fmaf(uv.w, wv.w, acc);
            }
            xdbl[(row0 + r) * 44 + c] = acc;
            if (c < Rr) sdt[r][c] = acc;
        }
    }
    __syncthreads();

    // dt_proj + softplus: 16 rows x 384 = 6144 outputs, 24 per thread
#pragma unroll
    for (int i = 0; i < 24; i++) {
        int idx = t + i * 256;
        int r   = idx / DI;
        int d   = idx % DI;
        float acc = dtb[d];
        const float* dw = &dtw[d * Rr];
#pragma unroll
        for (int j = 0; j < Rr; j++)
            acc = fmaf(sdt[r][j], dw[j], acc);
        delta[(row0 + r) * DI + d] = softplus_f(acc);
    }
}

// ---------------- selective scan: one 16-lane group per (b,d) -----------------
__global__ void scan_kernel(const float* __restrict__ xdbl,
                            const float* __restrict__ delta,
                            const float* __restrict__ u,
                            const float* __restrict__ A_log,
                            const float* __restrict__ Dp,
                            const int* __restrict__ perm,
                            float* __restrict__ y) {
    int t = threadIdx.x;                  // 256
    int g = blockIdx.x * 16 + (t >> 4);   // group id: 0..3071
    int s = t & 15;
    int b = g / DI;
    int d = g % DI;
    float A  = -expf(A_log[d * Ss + s]);
    float Dd = Dp[d];
    float h  = 0.f;
    int base = b * Ll;

    // prefetch l = 0
    float dl = delta[base * DI + d];
    float ul = u[base * DI + d];
    float Bs = xdbl[base * 44 + Rr + s];
    float Cs = xdbl[base * 44 + Rr + Ss + s];
    int   pl = perm[0];

    for (int l = 0; l < Ll; l++) {
        float dl2, ul2, Bs2, Cs2; int pl2;
        if (l + 1 < Ll) {
            int row = base + l + 1;
            dl2 = delta[row * DI + d];
            ul2 = u[row * DI + d];
            Bs2 = xdbl[row * 44 + Rr + s];
            Cs2 = xdbl[row * 44 + Rr + Ss + s];
            pl2 = perm[l + 1];
        }
        float dA = __expf(dl * A);
        h = fmaf(dA, h, dl * ul * Bs);
        float yv = h * Cs;
#pragma unroll
        for (int o = 8; o; o >>= 1) yv += __shfl_xor_sync(0xffffffffu, yv, o, 16);
        if (s == 0) y[(base + pl) * DI + d] = yv + ul * Dd;
        dl = dl2; ul = ul2; Bs = Bs2; Cs = Cs2; pl = pl2;
    }
}

// ---------------- launcher ----------------
extern "C" void kernel_launch(void* const* d_in, const int* in_sizes, int n_in,
                              void* d_out, int out_size) {
    const float* x          = (const float*)d_in[0];
    const int*   perm       = (const int*)  d_in[1];
    const int*   perm_rev   = (const int*)  d_in[2];
    const float* ln1_g      = (const float*)d_in[3];
    const float* ln1_b      = (const float*)d_in[4];
    const float* in_proj_w  = (const float*)d_in[5];
    const float* conv_w     = (const float*)d_in[6];
    const float* conv_b     = (const float*)d_in[7];
    const float* x_proj_w   = (const float*)d_in[8];
    const float* dt_proj_w  = (const float*)d_in[9];
    const float* dt_proj_b  = (const float*)d_in[10];
    const float* A_log      = (const float*)d_in[11];
    const float* Dp         = (const float*)d_in[12];
    const float* out_norm_g = (const float*)d_in[13];
    const float* out_norm_b = (const float*)d_in[14];
    const float* out_proj_w = (const float*)d_in[15];
    const float* ln2_g      = (const float*)d_in[16];
    const float* ln2_b      = (const float*)d_in[17];
    const float* fc1_w      = (const float*)d_in[18];
    const float* fc1_b      = (const float*)d_in[19];
    const float* fc2_w      = (const float*)d_in[20];
    const float* fc2_b      = (const float*)d_in[21];
    float* out = (float*)d_out;

    float *hx, *xz, *u, *xdbl, *delta, *y, *xmid, *h2, *m;
    cudaGetSymbolAddress((void**)&hx,    g_hx);
    cudaGetSymbolAddress((void**)&xz,    g_xz);
    cudaGetSymbolAddress((void**)&u,     g_u);
    cudaGetSymbolAddress((void**)&xdbl,  g_xdbl);
    cudaGetSymbolAddress((void**)&delta, g_delta);
    cudaGetSymbolAddress((void**)&y,     g_y);
    cudaGetSymbolAddress((void**)&xmid,  g_xmid);
    cudaGetSymbolAddress((void**)&h2,    g_h2);
    cudaGetSymbolAddress((void**)&m,     g_m);

    // 1. LN1
    ln_kernel<Cc><<<ROWS, Cc>>>(x, ln1_g, ln1_b, hx);
    // 2. in_proj: [8192,192] x [768,192]^T -> xz [8192,768]
    gemm2_kernel<0, false, false><<<dim3((2 * DI) / GBN, ROWS / GBM), 256>>>(
        hx, Cc, in_proj_w, nullptr, nullptr, xz, ROWS, 2 * DI, Cc);
    // 3. depthwise conv + SiLU + zigzag scatter -> u [8192,384]
    conv_silu_kernel<<<ROWS, DI>>>(xz, conv_w, conv_b, perm_rev, u);
    // 4+5. fused x_proj + dt_proj + softplus
    xdt_kernel<<<ROWS / 16, 256>>>(u, x_proj_w, dt_proj_w, dt_proj_b, xdbl, delta);
    // 6. selective scan + Dp skip + un-zigzag scatter -> y (spatial order)
    scan_kernel<<<(Bn * DI) / 16, 256>>>(xdbl, delta, u, A_log, Dp, perm, y);
    // 7. out_norm LN + silu(z) gate (in-place on y)
    gate_ln_kernel<<<ROWS, DI>>>(y, xz, out_norm_g, out_norm_b, y);
    // 8. out_proj + residual x -> xmid [8192,192]
    gemm2_kernel<0, false, true><<<dim3(Cc / GBN, ROWS / GBM), 256>>>(
        y, DI, out_proj_w, nullptr, x, xmid, ROWS, Cc, DI);
    // 9. LN2
    ln_kernel<Cc><<<ROWS, Cc>>>(xmid, ln2_g, ln2_b, h2);
    // 10. fc1 + bias + gelu -> m [8192,768]
    gemm2_kernel<2, true, false><<<dim3(HID / GBN, ROWS / GBM), 256>>>(
        h2, Cc, fc1_w, fc1_b, nullptr, m, ROWS, HID, Cc);
    // 11. fc2 + bias + residual xmid -> out [8192,192]
    gemm2_kernel<0, true, true><<<dim3(Cc / GBN, ROWS / GBM), 256>>>(
        m, HID, fc2_w, fc2_b, xmid, out, ROWS, Cc, HID);
}

// round 4
// speedup vs baseline: 1.3161x; 1.2891x over previous
#include <cuda_runtime.h>
#include <math.h>
#include <stdint.h>

// Problem constants
#define Bn   8
#define Hh   32
#define Ww   32
#define Cc   192
#define DI   384
#define Ss   16
#define Rr   12
#define HID  768
#define Ll   1024          // H*W
#define ROWS (Bn * Ll)     // 8192

// ---------------- scratch (no allocation allowed) ----------------
__device__ float g_hx   [ROWS * Cc];
__device__ float g_xz   [ROWS * (2 * DI)];
__device__ float g_u    [ROWS * DI];
__device__ float g_xdbl [ROWS * 44];
__device__ float g_delta[ROWS * DI];
__device__ float g_y    [ROWS * DI];
__device__ float g_xmid [ROWS * Cc];
__device__ float g_h2   [ROWS * Cc];
__device__ float g_m    [ROWS * HID];

// ---------------- device math helpers ----------------
__device__ __forceinline__ float silu_f(float x) {
    return x / (1.0f + __expf(-x));
}
__device__ __forceinline__ float softplus_f(float x) {
    return (x > 20.0f) ? x : log1pf(expf(x));
}
__device__ __forceinline__ float gelu_f(float x) {
    float x3 = x * x * x;
    return 0.5f * x * (1.0f + tanhf(0.7978845608028654f * (x + 0.044715f * x3)));
}
__device__ __forceinline__ uint32_t tf32_of(float x) {
    uint32_t r;
    asm("cvt.rna.tf32.f32 %0, %1;" : "=r"(r) : "f"(x));
    return r;
}
__device__ __forceinline__ void mma_tf32(float& c0, float& c1, float& c2, float& c3,
                                         uint32_t a0, uint32_t a1, uint32_t a2, uint32_t a3,
                                         uint32_t b0, uint32_t b1) {
    asm volatile(
        "mma.sync.aligned.m16n8k8.row.col.f32.tf32.tf32.f32 "
        "{%0,%1,%2,%3}, {%4,%5,%6,%7}, {%8,%9}, {%0,%1,%2,%3};\n"
        : "+f"(c0), "+f"(c1), "+f"(c2), "+f"(c3)
        : "r"(a0), "r"(a1), "r"(a2), "r"(a3), "r"(b0), "r"(b1));
}

// ---------------- LayerNorm (one block per row, blockDim == C) ----------------
template <int C>
__global__ void ln_kernel(const float* __restrict__ x,
                          const float* __restrict__ g,
                          const float* __restrict__ b,
                          float* __restrict__ out) {
    int row = blockIdx.x;
    int t   = threadIdx.x;
    float v = x[row * C + t];
    float s = v, s2 = v * v;
    __shared__ float sh[C / 32], sh2[C / 32];
#pragma unroll
    for (int o = 16; o; o >>= 1) {
        s  += __shfl_xor_sync(0xffffffffu, s,  o);
        s2 += __shfl_xor_sync(0xffffffffu, s2, o);
    }
    if ((t & 31) == 0) { sh[t >> 5] = s; sh2[t >> 5] = s2; }
    __syncthreads();
    float mean = 0.f, m2 = 0.f;
#pragma unroll
    for (int i = 0; i < C / 32; i++) { mean += sh[i]; m2 += sh2[i]; }
    mean *= (1.0f / C);
    float var = m2 * (1.0f / C) - mean * mean;
    float inv = rsqrtf(var + 1e-5f);
    out[row * C + t] = (v - mean) * inv * g[t] + b[t];
}

// ---------------- out_norm LN + silu(z) gating (C = DI = 384) ----------------
__global__ void gate_ln_kernel(const float* __restrict__ y,
                               const float* __restrict__ xz,
                               const float* __restrict__ g,
                               const float* __restrict__ b,
                               float* __restrict__ out) {
    int row = blockIdx.x;
    int t   = threadIdx.x;           // 384
    float v = y[row * DI + t];
    float s = v, s2 = v * v;
    __shared__ float sh[DI / 32], sh2[DI / 32];
#pragma unroll
    for (int o = 16; o; o >>= 1) {
        s  += __shfl_xor_sync(0xffffffffu, s,  o);
        s2 += __shfl_xor_sync(0xffffffffu, s2, o);
    }
    if ((t & 31) == 0) { sh[t >> 5] = s; sh2[t >> 5] = s2; }
    __syncthreads();
    float mean = 0.f, m2 = 0.f;
#pragma unroll
    for (int i = 0; i < DI / 32; i++) { mean += sh[i]; m2 += sh2[i]; }
    mean *= (1.0f / DI);
    float var = m2 * (1.0f / DI) - mean * mean;
    float inv = rsqrtf(var + 1e-5f);
    float ln  = (v - mean) * inv * g[t] + b[t];
    float zz  = xz[row * (2 * DI) + DI + t];
    out[row * DI + t] = ln * silu_f(zz);
}

// ============ TF32 tensor-core GEMM: C[M,N] = A[M,K(lda)] * W[N,K]^T ==========
// 128x64 block tile, 256 threads = 8 warps, each warp a 32x32 tile made of
// 2x4 m16n8k8 tf32 mma atoms. BK=32. Requires M%128==0, N%64==0, K%32==0.
// ACT: 0 none, 1 softplus, 2 gelu
#define TBM 128
#define TBN 64
#define TBK 32

template <int ACT, bool HAS_BIAS, bool HAS_RES>
__global__ __launch_bounds__(256)
void gemm_tc(const float* __restrict__ A, int lda,
             const float* __restrict__ W,
             const float* __restrict__ bias,
             const float* __restrict__ res,
             float* __restrict__ Cout,
             int M, int N, int K) {
    __shared__ float As[TBM][TBK + 4];   // [m][k], pad 36 -> conflict-free frags
    __shared__ float Ws[TBN][TBK + 4];   // [n][k]

    int t    = threadIdx.x;
    int lane = t & 31;
    int wid  = t >> 5;
    int wm   = (wid & 3) * 32;           // warp M offset in tile
    int wn   = (wid >> 2) * 32;          // warp N offset in tile
    int gid  = lane >> 2;                // 0..7
    int tig  = lane & 3;                 // 0..3
    int row0 = blockIdx.y * TBM;
    int col0 = blockIdx.x * TBN;

    int lr = t >> 3;                     // 0..31
    int lc = (t & 7) * 4;                // 0,4,..,28

    float acc[2][4][4];
#pragma unroll
    for (int i = 0; i < 2; i++)
#pragma unroll
        for (int j = 0; j < 4; j++)
#pragma unroll
            for (int q = 0; q < 4; q++) acc[i][j][q] = 0.f;

    float4 ra[4], rw[2];
#pragma unroll
    for (int i = 0; i < 4; i++)
        ra[i] = *(const float4*)&A[(row0 + lr + i * 32) * lda + lc];
#pragma unroll
    for (int i = 0; i < 2; i++)
        rw[i] = *(const float4*)&W[(col0 + lr + i * 32) * K + lc];

    for (int k0 = 0; k0 < K; k0 += TBK) {
        __syncthreads();
#pragma unroll
        for (int i = 0; i < 4; i++) {
            As[lr + i * 32][lc + 0] = __uint_as_float(tf32_of(ra[i].x));
            As[lr + i * 32][lc + 1] = __uint_as_float(tf32_of(ra[i].y));
            As[lr + i * 32][lc + 2] = __uint_as_float(tf32_of(ra[i].z));
            As[lr + i * 32][lc + 3] = __uint_as_float(tf32_of(ra[i].w));
        }
#pragma unroll
        for (int i = 0; i < 2; i++) {
            Ws[lr + i * 32][lc + 0] = __uint_as_float(tf32_of(rw[i].x));
            Ws[lr + i * 32][lc + 1] = __uint_as_float(tf32_of(rw[i].y));
            Ws[lr + i * 32][lc + 2] = __uint_as_float(tf32_of(rw[i].z));
            Ws[lr + i * 32][lc + 3] = __uint_as_float(tf32_of(rw[i].w));
        }
        __syncthreads();

        int kn = k0 + TBK;
        if (kn < K) {
#pragma unroll
            for (int i = 0; i < 4; i++)
                ra[i] = *(const float4*)&A[(row0 + lr + i * 32) * lda + kn + lc];
#pragma unroll
            for (int i = 0; i < 2; i++)
                rw[i] = *(const float4*)&W[(col0 + lr + i * 32) * K + kn + lc];
        }

#pragma unroll
        for (int k8 = 0; k8 < 4; k8++) {
            int kk = k8 * 8;
            uint32_t af[2][4], bf[4][2];
#pragma unroll
            for (int i = 0; i < 2; i++) {
                int r = wm + i * 16 + gid;
                af[i][0] = __float_as_uint(As[r][kk + tig]);
                af[i][1] = __float_as_uint(As[r + 8][kk + tig]);
                af[i][2] = __float_as_uint(As[r][kk + tig + 4]);
                af[i][3] = __float_as_uint(As[r + 8][kk + tig + 4]);
            }
#pragma unroll
            for (int j = 0; j < 4; j++) {
                int n = wn + j * 8 + gid;
                bf[j][0] = __float_as_uint(Ws[n][kk + tig]);
                bf[j][1] = __float_as_uint(Ws[n][kk + tig + 4]);
            }
#pragma unroll
            for (int i = 0; i < 2; i++)
#pragma unroll
                for (int j = 0; j < 4; j++)
                    mma_tf32(acc[i][j][0], acc[i][j][1], acc[i][j][2], acc[i][j][3],
                             af[i][0], af[i][1], af[i][2], af[i][3],
                             bf[j][0], bf[j][1]);
        }
    }

    // epilogue: c0,c1 -> (row, col..col+1); c2,c3 -> (row+8, col..col+1)
#pragma unroll
    for (int i = 0; i < 2; i++) {
        int rA = row0 + wm + i * 16 + gid;
#pragma unroll
        for (int j = 0; j < 4; j++) {
            int col = col0 + wn + j * 8 + tig * 2;
            float b0 = 0.f, b1 = 0.f;
            if (HAS_BIAS) { b0 = bias[col]; b1 = bias[col + 1]; }
            float v0 = acc[i][j][0] + b0;
            float v1 = acc[i][j][1] + b1;
            float v2 = acc[i][j][2] + b0;
            float v3 = acc[i][j][3] + b1;
            if (ACT == 1) { v0 = softplus_f(v0); v1 = softplus_f(v1);
                            v2 = softplus_f(v2); v3 = softplus_f(v3); }
            else if (ACT == 2) { v0 = gelu_f(v0); v1 = gelu_f(v1);
                                 v2 = gelu_f(v2); v3 = gelu_f(v3); }
            if (HAS_RES) {
                float2 r0 = *(const float2*)&res[rA * N + col];
                float2 r1 = *(const float2*)&res[(rA + 8) * N + col];
                v0 += r0.x; v1 += r0.y; v2 += r1.x; v3 += r1.y;
            }
            *(float2*)&Cout[rA * N + col]       = make_float2(v0, v1);
            *(float2*)&Cout[(rA + 8) * N + col] = make_float2(v2, v3);
        }
    }
}

// ---------------- depthwise 3x3 conv + bias + SiLU, scatter to zigzag order ----
__global__ void conv_silu_kernel(const float* __restrict__ xz,
                                 const float* __restrict__ cw,
                                 const float* __restrict__ cb,
                                 const int* __restrict__ perm_rev,
                                 float* __restrict__ u) {
    int bp = blockIdx.x;            // b*1024 + p
    int b  = bp >> 10;
    int p  = bp & 1023;
    int h  = p >> 5;
    int w  = p & 31;
    int d  = threadIdx.x;           // 384
    float acc = cb[d];
#pragma unroll
    for (int kh = 0; kh < 3; kh++) {
        int nh = h + kh - 1;
        if ((unsigned)nh >= (unsigned)Hh) continue;
#pragma unroll
        for (int kw = 0; kw < 3; kw++) {
            int nw = w + kw - 1;
            if ((unsigned)nw >= (unsigned)Ww) continue;
            acc = fmaf(cw[d * 9 + kh * 3 + kw],
                       xz[((b << 10) + (nh << 5) + nw) * (2 * DI) + d], acc);
        }
    }
    u[((b << 10) + perm_rev[p]) * DI + d] = silu_f(acc);
}

// ========== fused x_proj + dt_proj + softplus (16 rows per block) ==========
// su stored transposed [k][r] -> conflict-free broadcast reads.
__global__ __launch_bounds__(256)
void xdt_kernel(const float* __restrict__ u,
                const float* __restrict__ xw,     // [44,384]
                const float* __restrict__ dtw,    // [384,12]
                const float* __restrict__ dtb,    // [384]
                float* __restrict__ xdbl,         // [ROWS,44]
                float* __restrict__ delta) {      // [ROWS,DI]
    __shared__ float su[DI][17];                  // [k][r], 26KB
    __shared__ float sdt[16][12];
    int t    = threadIdx.x;
    int row0 = blockIdx.x * 16;

    // load u rows transposed: 1536 float4, 6 per thread
#pragma unroll
    for (int i = 0; i < 6; i++) {
        int idx = t + i * 256;
        int r   = idx / 96;
        int c4  = (idx % 96) * 4;
        float4 v = *(const float4*)&u[(row0 + r) * DI + c4];
        su[c4 + 0][r] = v.x;
        su[c4 + 1][r] = v.y;
        su[c4 + 2][r] = v.z;
        su[c4 + 3][r] = v.w;
    }
    __syncthreads();

    // x_proj: 16 rows x 44 cols = 704 dots of K=384
#pragma unroll
    for (int p = 0; p < 3; p++) {
        int idx = t + p * 256;
        if (idx < 704) {
            int r = idx & 15;
            int c = idx >> 4;       // 0..43
            const float4* wr = (const float4*)&xw[c * DI];
            float acc = 0.f;
#pragma unroll 8
            for (int k = 0; k < DI; k += 4) {
                float4 wv = wr[k >> 2];
                acc = fmaf(su[k + 0][r], wv.x, acc);
                acc = fmaf(su[k + 1][r], wv.y, acc);
                acc = fmaf(su[k + 2][r], wv.z, acc);
                acc = fmaf(su[k + 3][r], wv.w, acc);
            }
            xdbl[(row0 + r) * 44 + c] = acc;
            if (c < Rr) sdt[r][c] = acc;
        }
    }
    __syncthreads();

    // dt_proj + softplus: 16 rows x 384 = 6144 outputs, 24 per thread
#pragma unroll
    for (int i = 0; i < 24; i++) {
        int idx = t + i * 256;
        int r   = idx / DI;
        int d   = idx % DI;
        float acc = dtb[d];
        const float* dw = &dtw[d * Rr];
#pragma unroll
        for (int j = 0; j < Rr; j++)
            acc = fmaf(sdt[r][j], dw[j], acc);
        delta[(row0 + r) * DI + d] = softplus_f(acc);
    }
}

// ---------------- selective scan: one 16-lane group per (b,d) -----------------
__global__ void scan_kernel(const float* __restrict__ xdbl,
                            const float* __restrict__ delta,
                            const float* __restrict__ u,
                            const float* __restrict__ A_log,
                            const float* __restrict__ Dp,
                            const int* __restrict__ perm,
                            float* __restrict__ y) {
    int t = threadIdx.x;                  // 256
    int g = blockIdx.x * 16 + (t >> 4);   // group id: 0..3071
    int s = t & 15;
    int b = g / DI;
    int d = g % DI;
    float A  = -expf(A_log[d * Ss + s]);
    float Dd = Dp[d];
    float h  = 0.f;
    int base = b * Ll;

    // prefetch l = 0
    float dl = delta[base * DI + d];
    float ul = u[base * DI + d];
    float Bs = xdbl[base * 44 + Rr + s];
    float Cs = xdbl[base * 44 + Rr + Ss + s];
    int   pl = perm[0];

    for (int l = 0; l < Ll; l++) {
        float dl2, ul2, Bs2, Cs2; int pl2;
        if (l + 1 < Ll) {
            int row = base + l + 1;
            dl2 = delta[row * DI + d];
            ul2 = u[row * DI + d];
            Bs2 = xdbl[row * 44 + Rr + s];
            Cs2 = xdbl[row * 44 + Rr + Ss + s];
            pl2 = perm[l + 1];
        }
        float dA = __expf(dl * A);
        h = fmaf(dA, h, dl * ul * Bs);
        float yv = h * Cs;
#pragma unroll
        for (int o = 8; o; o >>= 1) yv += __shfl_xor_sync(0xffffffffu, yv, o, 16);
        if (s == 0) y[(base + pl) * DI + d] = yv + ul * Dd;
        dl = dl2; ul = ul2; Bs = Bs2; Cs = Cs2; pl = pl2;
    }
}

// ---------------- launcher ----------------
extern "C" void kernel_launch(void* const* d_in, const int* in_sizes, int n_in,
                              void* d_out, int out_size) {
    const float* x          = (const float*)d_in[0];
    const int*   perm       = (const int*)  d_in[1];
    const int*   perm_rev   = (const int*)  d_in[2];
    const float* ln1_g      = (const float*)d_in[3];
    const float* ln1_b      = (const float*)d_in[4];
    const float* in_proj_w  = (const float*)d_in[5];
    const float* conv_w     = (const float*)d_in[6];
    const float* conv_b     = (const float*)d_in[7];
    const float* x_proj_w   = (const float*)d_in[8];
    const float* dt_proj_w  = (const float*)d_in[9];
    const float* dt_proj_b  = (const float*)d_in[10];
    const float* A_log      = (const float*)d_in[11];
    const float* Dp         = (const float*)d_in[12];
    const float* out_norm_g = (const float*)d_in[13];
    const float* out_norm_b = (const float*)d_in[14];
    const float* out_proj_w = (const float*)d_in[15];
    const float* ln2_g      = (const float*)d_in[16];
    const float* ln2_b      = (const float*)d_in[17];
    const float* fc1_w      = (const float*)d_in[18];
    const float* fc1_b      = (const float*)d_in[19];
    const float* fc2_w      = (const float*)d_in[20];
    const float* fc2_b      = (const float*)d_in[21];
    float* out = (float*)d_out;

    float *hx, *xz, *u, *xdbl, *delta, *y, *xmid, *h2, *m;
    cudaGetSymbolAddress((void**)&hx,    g_hx);
    cudaGetSymbolAddress((void**)&xz,    g_xz);
    cudaGetSymbolAddress((void**)&u,     g_u);
    cudaGetSymbolAddress((void**)&xdbl,  g_xdbl);
    cudaGetSymbolAddress((void**)&delta, g_delta);
    cudaGetSymbolAddress((void**)&y,     g_y);
    cudaGetSymbolAddress((void**)&xmid,  g_xmid);
    cudaGetSymbolAddress((void**)&h2,    g_h2);
    cudaGetSymbolAddress((void**)&m,     g_m);

    // 1. LN1
    ln_kernel<Cc><<<ROWS, Cc>>>(x, ln1_g, ln1_b, hx);
    // 2. in_proj: [8192,192] x [768,192]^T -> xz [8192,768]   (TF32 TC)
    gemm_tc<0, false, false><<<dim3((2 * DI) / TBN, ROWS / TBM), 256>>>(
        hx, Cc, in_proj_w, nullptr, nullptr, xz, ROWS, 2 * DI, Cc);
    // 3. depthwise conv + SiLU + zigzag scatter -> u [8192,384]
    conv_silu_kernel<<<ROWS, DI>>>(xz, conv_w, conv_b, perm_rev, u);
    // 4+5. fused x_proj + dt_proj + softplus (fp32 for scan precision)
    xdt_kernel<<<ROWS / 16, 256>>>(u, x_proj_w, dt_proj_w, dt_proj_b, xdbl, delta);
    // 6. selective scan + Dp skip + un-zigzag scatter -> y (spatial order)
    scan_kernel<<<(Bn * DI) / 16, 256>>>(xdbl, delta, u, A_log, Dp, perm, y);
    // 7. out_norm LN + silu(z) gate (in-place on y)
    gate_ln_kernel<<<ROWS, DI>>>(y, xz, out_norm_g, out_norm_b, y);
    // 8. out_proj + residual x -> xmid [8192,192]   (TF32 TC)
    gemm_tc<0, false, true><<<dim3(Cc / TBN, ROWS / TBM), 256>>>(
        y, DI, out_proj_w, nullptr, x, xmid, ROWS, Cc, DI);
    // 9. LN2
    ln_kernel<Cc><<<ROWS, Cc>>>(xmid, ln2_g, ln2_b, h2);
    // 10. fc1 + bias + gelu -> m [8192,768]   (TF32 TC)
    gemm_tc<2, true, false><<<dim3(HID / TBN, ROWS / TBM), 256>>>(
        h2, Cc, fc1_w, fc1_b, nullptr, m, ROWS, HID, Cc);
    // 11. fc2 + bias + residual xmid -> out [8192,192]   (TF32 TC)
    gemm_tc<0, true, true><<<dim3(Cc / TBN, ROWS / TBM), 256>>>(
        m, HID, fc2_w, fc2_b, xmid, out, ROWS, Cc, HID);
}